// round 16
// baseline (speedup 1.0000x reference)
#include <cuda_runtime.h>
#include <math.h>

// Shapes (fixed by setup_inputs): B=4, N=64, T=64, FH=128, FO=64
#define N_  64
#define T_  64
#define FH_ 128
#define FO_ 64

// Scratch (device global; no allocation allowed). Every element [0,E) is
// overwritten by edge_kernel each launch -> no zeroing needed.
__device__ int g_eidx[4096];

// ---------------------------------------------------------------------------
// packed fp32x2 helpers (Blackwell FFMA2 — only reachable via PTX)
// ---------------------------------------------------------------------------
__device__ __forceinline__ unsigned long long fma2(unsigned long long a,
                                                   unsigned long long b,
                                                   unsigned long long c) {
    unsigned long long d;
    asm("fma.rn.f32x2 %0, %1, %2, %3;" : "=l"(d) : "l"(a), "l"(b), "l"(c));
    return d;
}
__device__ __forceinline__ unsigned long long pack2(float x, float y) {
    unsigned long long d;
    asm("mov.b64 %0, {%1, %2};" : "=l"(d)
        : "r"(__float_as_uint(x)), "r"(__float_as_uint(y)));
    return d;
}
__device__ __forceinline__ float lo2(unsigned long long v) {
    return __uint_as_float((unsigned)v);
}
__device__ __forceinline__ float hi2(unsigned long long v) {
    return __uint_as_float((unsigned)(v >> 32));
}

// ---------------------------------------------------------------------------
// Kernel 1: edge indices via argmax (float4 loads, first-max rule).
// ---------------------------------------------------------------------------
__global__ void edge_kernel(const float* __restrict__ rr,
                            const float* __restrict__ rs, int E)
{
    int e = blockIdx.x * blockDim.x + threadIdx.x;
    if (e >= E) return;
    const float4* r4 = reinterpret_cast<const float4*>(rr) + (size_t)e * 16;
    const float4* s4 = reinterpret_cast<const float4*>(rs) + (size_t)e * 16;
    float mr = -1e30f, ms = -1e30f;
    int ir = 0, is = 0;
    #pragma unroll
    for (int j = 0; j < 16; j++) {
        float4 v = r4[j];
        if (v.x > mr) { mr = v.x; ir = j * 4 + 0; }
        if (v.y > mr) { mr = v.y; ir = j * 4 + 1; }
        if (v.z > mr) { mr = v.z; ir = j * 4 + 2; }
        if (v.w > mr) { mr = v.w; ir = j * 4 + 3; }
        float4 w = s4[j];
        if (w.x > ms) { ms = w.x; is = j * 4 + 0; }
        if (w.y > ms) { ms = w.y; is = j * 4 + 1; }
        if (w.z > ms) { ms = w.z; is = j * 4 + 2; }
        if (w.w > ms) { ms = w.w; is = j * 4 + 3; }
    }
    g_eidx[e] = ir * N_ + is;
}

// ---------------------------------------------------------------------------
// Kernel 2: FUSED. One block per (b,t), 256 threads, 2 blocks/SM.
//   P1: stage h[b,:,t,:], W^T, a_w
//   P2: GEMM1  Wh = h @ W^T + b  -> swh  (4n x 4o per thread, FFMA2)
//   P3: pr/ps = swh · a_r/a_s (warps 0-3) ; zero score tile (warps 4-7)
//       NOTE: sa overlays sh (dead after GEMM1)
//   P4: edge scatter: sa[r][s] += exp(lrelu(pr[r]+ps[s]+ab))  (smem atomics)
//   P5: row sums ; write A / A_sym ; normalize -> A_norm
//   P6: GEMM2  h_p = relu(A_norm @ Wh)
// smem: sh[64][132]@0 (sa[64][68] overlays @0), swt[128][68]@8448,
//       swh[64][68]@17152, spr/sps/sinv/saw after  -> 21824 floats = 87.3 KB
// ---------------------------------------------------------------------------
#define SH_STRIDE  132
#define SWT_STRIDE 68
#define SA_STRIDE  68
#define SWH_STRIDE 68
#define OFF_WT  8448
#define OFF_WH  (OFF_WT + 128*68)     // 17152
#define OFF_PR  (OFF_WH + 64*68)      // 21504
#define OFF_PS  (OFF_PR + 64)
#define OFF_INV (OFF_PS + 64)
#define OFF_AW  (OFF_INV + 64)
#define SMEM_FLOATS (OFF_AW + 128)    // 21824 floats = 87296 B

__global__ void __launch_bounds__(256, 2)
fused_kernel(const float* __restrict__ h,    // [B][N][T][FH]
             const float* __restrict__ W,    // [FO][FH]
             const float* __restrict__ bfc,  // [FO]
             const float* __restrict__ aw,   // [2*FO]
             const float* __restrict__ ab_ptr,
             float* __restrict__ out, int B, int E)
{
    extern __shared__ float sm[];
    float* sh   = sm;             // [64][132]  (P1-P2 only)
    float* sa   = sm;             // [64][68]   (P3 onward, overlays sh)
    float* swt  = sm + OFF_WT;    // [128][68]
    float* swh  = sm + OFF_WH;    // [64][68]
    float* spr  = sm + OFF_PR;
    float* sps  = sm + OFF_PS;
    float* sinv = sm + OFF_INV;
    float* saw  = sm + OFF_AW;    // [128]

    const int t   = blockIdx.x;
    const int b   = blockIdx.y;
    const int tid = threadIdx.x;

    // ---- P1: stage ----
    #pragma unroll
    for (int i = 0; i < 8; i++) {
        int idx = tid + i * 256;          // 0..2047
        int n = idx >> 5, c4 = (idx & 31) * 4;
        float4 v = *reinterpret_cast<const float4*>(
            h + ((size_t)(b * N_ + n) * T_ + t) * FH_ + c4);
        *reinterpret_cast<float4*>(&sh[n * SH_STRIDE + c4]) = v;
    }
    {   // W^T: [k][o]  (each thread: 8 float4 = 32 k values of one o)
        int o = tid >> 2, kc = (tid & 3) * 32;
        const float4* wrow = reinterpret_cast<const float4*>(W + o * FH_ + kc);
        #pragma unroll
        for (int j = 0; j < 8; j++) {
            float4 v = wrow[j];
            int k = kc + j * 4;
            swt[(k + 0) * SWT_STRIDE + o] = v.x;
            swt[(k + 1) * SWT_STRIDE + o] = v.y;
            swt[(k + 2) * SWT_STRIDE + o] = v.z;
            swt[(k + 3) * SWT_STRIDE + o] = v.w;
        }
    }
    if (tid < 128) saw[tid] = aw[tid];
    __syncthreads();

    // ---- P2: GEMM1  Wh[n][o] = sum_k h[n][k] * W^T[k][o] + b[o] ----
    const int ni = tid >> 4;     // 0..15 -> rows ni*4 .. ni*4+3
    const int oi = tid & 15;     // 0..15 -> cols oi*4 .. oi*4+3
    const int o0 = oi * 4;
    {
        unsigned long long bv0 = pack2(bfc[o0 + 0], bfc[o0 + 1]);
        unsigned long long bv1 = pack2(bfc[o0 + 2], bfc[o0 + 3]);
        unsigned long long acc[8];
        #pragma unroll
        for (int r = 0; r < 4; r++) { acc[2 * r] = bv0; acc[2 * r + 1] = bv1; }

        const float* hb = sh + (ni * 4) * SH_STRIDE;
        #pragma unroll 4
        for (int k4 = 0; k4 < 32; k4++) {
            float a0[4], a1[4], a2[4], a3[4];
            *reinterpret_cast<float4*>(a0) = *reinterpret_cast<const float4*>(hb + 0 * SH_STRIDE + k4 * 4);
            *reinterpret_cast<float4*>(a1) = *reinterpret_cast<const float4*>(hb + 1 * SH_STRIDE + k4 * 4);
            *reinterpret_cast<float4*>(a2) = *reinterpret_cast<const float4*>(hb + 2 * SH_STRIDE + k4 * 4);
            *reinterpret_cast<float4*>(a3) = *reinterpret_cast<const float4*>(hb + 3 * SH_STRIDE + k4 * 4);
            #pragma unroll
            for (int kk = 0; kk < 4; kk++) {
                ulonglong2 w = *reinterpret_cast<const ulonglong2*>(
                    swt + (k4 * 4 + kk) * SWT_STRIDE + o0);
                unsigned long long h0 = pack2(a0[kk], a0[kk]);
                unsigned long long h1 = pack2(a1[kk], a1[kk]);
                unsigned long long h2 = pack2(a2[kk], a2[kk]);
                unsigned long long h3 = pack2(a3[kk], a3[kk]);
                acc[0] = fma2(h0, w.x, acc[0]); acc[1] = fma2(h0, w.y, acc[1]);
                acc[2] = fma2(h1, w.x, acc[2]); acc[3] = fma2(h1, w.y, acc[3]);
                acc[4] = fma2(h2, w.x, acc[4]); acc[5] = fma2(h2, w.y, acc[5]);
                acc[6] = fma2(h3, w.x, acc[6]); acc[7] = fma2(h3, w.y, acc[7]);
            }
        }
        #pragma unroll
        for (int r = 0; r < 4; r++) {
            float4 v = make_float4(lo2(acc[2 * r]), hi2(acc[2 * r]),
                                   lo2(acc[2 * r + 1]), hi2(acc[2 * r + 1]));
            *reinterpret_cast<float4*>(swh + (ni * 4 + r) * SWH_STRIDE + o0) = v;
        }
    }
    __syncthreads();

    // ---- P3: pr/ps (warps 0-3) ; zero sa (warps 4-7) ----
    if (tid < 128) {
        int n = tid & 63;
        const float* wr = swh + n * SWH_STRIDE;
        const float* av = (tid < 64) ? saw : (saw + 64);
        float a = 0.f;
        #pragma unroll
        for (int j = 0; j < 16; j++) {
            float4 wv  = *reinterpret_cast<const float4*>(wr + j * 4);
            float4 avv = *reinterpret_cast<const float4*>(av + j * 4);
            a = fmaf(wv.x, avv.x, a); a = fmaf(wv.y, avv.y, a);
            a = fmaf(wv.z, avv.z, a); a = fmaf(wv.w, avv.w, a);
        }
        if (tid < 64) spr[n] = a; else sps[n] = a;
    } else {
        int base = tid - 128;   // 0..127, 64*68=4352 floats to zero
        #pragma unroll
        for (int i = 0; i < 34; i++) sa[base + i * 128] = 0.f;
    }
    __syncthreads();

    // ---- P4: edge scatter into sa ----
    const float ab = ab_ptr[0];
    for (int e = tid; e < E; e += 256) {
        int idx = g_eidx[e];
        int r = idx >> 6, s = idx & 63;
        float x = spr[r] + sps[s] + ab;
        x = (x > 0.f) ? x : 0.2f * x;
        atomicAdd(&sa[r * SA_STRIDE + s], __expf(x));
    }
    __syncthreads();

    // ---- P5: row sums, write A / A_sym, normalize -> A_norm ----
    if (tid < 64) {
        const float* row = sa + tid * SA_STRIDE;
        float s0 = 0.f, s1 = 0.f, s2 = 0.f, s3 = 0.f;
        #pragma unroll
        for (int j = 0; j < 16; j++) {
            float4 v = *reinterpret_cast<const float4*>(row + j * 4);
            s0 += v.x; s1 += v.y; s2 += v.z; s3 += v.w;
        }
        sinv[tid] = __fdividef(1.f, (s0 + s1) + (s2 + s3));
    }

    const size_t npp = (size_t)B * T_ * N_ * N_;
    float* A_out     = out + (size_t)B * N_ * T_ * FO_;
    float* Asym_out  = A_out + npp;
    float* Anorm_out = Asym_out + npp;
    const size_t abase = ((size_t)(b * T_ + t)) * (N_ * N_);

    #pragma unroll
    for (int i = 0; i < 16; i++) {
        int idx = tid + i * 256;
        int r = idx >> 6, s = idx & 63;
        float v = sa[r * SA_STRIDE + s];
        A_out[abase + idx]    = v;
        Asym_out[abase + idx] = 0.5f * (v + sa[s * SA_STRIDE + r]);
    }
    __syncthreads();

    #pragma unroll
    for (int i = 0; i < 16; i++) {
        int idx = tid + i * 256;
        int r = idx >> 6, s = idx & 63;
        float v = sa[r * SA_STRIDE + s] * sinv[r];
        Anorm_out[abase + idx] = v;
        sa[r * SA_STRIDE + s] = v;
    }
    __syncthreads();

    // ---- P6: GEMM2  h_p[n][o] = relu( sum_m Anorm[n][m] * Wh[m][o] ) ----
    {
        unsigned long long acc[8];
        #pragma unroll
        for (int i = 0; i < 8; i++) acc[i] = 0ull;

        const float* arow = sa + (ni * 4) * SA_STRIDE;
        #pragma unroll 4
        for (int m4 = 0; m4 < 16; m4++) {
            float a0[4], a1[4], a2[4], a3[4];
            *reinterpret_cast<float4*>(a0) = *reinterpret_cast<const float4*>(arow + 0 * SA_STRIDE + m4 * 4);
            *reinterpret_cast<float4*>(a1) = *reinterpret_cast<const float4*>(arow + 1 * SA_STRIDE + m4 * 4);
            *reinterpret_cast<float4*>(a2) = *reinterpret_cast<const float4*>(arow + 2 * SA_STRIDE + m4 * 4);
            *reinterpret_cast<float4*>(a3) = *reinterpret_cast<const float4*>(arow + 3 * SA_STRIDE + m4 * 4);
            #pragma unroll
            for (int mm = 0; mm < 4; mm++) {
                ulonglong2 w = *reinterpret_cast<const ulonglong2*>(
                    swh + (m4 * 4 + mm) * SWH_STRIDE + o0);
                unsigned long long h0 = pack2(a0[mm], a0[mm]);
                unsigned long long h1 = pack2(a1[mm], a1[mm]);
                unsigned long long h2 = pack2(a2[mm], a2[mm]);
                unsigned long long h3 = pack2(a3[mm], a3[mm]);
                acc[0] = fma2(h0, w.x, acc[0]); acc[1] = fma2(h0, w.y, acc[1]);
                acc[2] = fma2(h1, w.x, acc[2]); acc[3] = fma2(h1, w.y, acc[3]);
                acc[4] = fma2(h2, w.x, acc[4]); acc[5] = fma2(h2, w.y, acc[5]);
                acc[6] = fma2(h3, w.x, acc[6]); acc[7] = fma2(h3, w.y, acc[7]);
            }
        }
        #pragma unroll
        for (int r = 0; r < 4; r++) {
            int n = ni * 4 + r;
            float4 v = make_float4(fmaxf(lo2(acc[2 * r]), 0.f),
                                   fmaxf(hi2(acc[2 * r]), 0.f),
                                   fmaxf(lo2(acc[2 * r + 1]), 0.f),
                                   fmaxf(hi2(acc[2 * r + 1]), 0.f));
            *reinterpret_cast<float4*>(out + (size_t)b * (N_ * T_ * FO_)
                                       + (size_t)n * (T_ * FO_)
                                       + (size_t)t * FO_ + o0) = v;
        }
    }
}

// ---------------------------------------------------------------------------
extern "C" void kernel_launch(void* const* d_in, const int* in_sizes, int n_in,
                              void* d_out, int out_size)
{
    const float* h   = (const float*)d_in[0];
    const float* rr  = (const float*)d_in[1];
    const float* rs  = (const float*)d_in[2];
    const float* Wfc = (const float*)d_in[3];
    const float* bfc = (const float*)d_in[4];
    const float* aw  = (const float*)d_in[5];
    const float* abp = (const float*)d_in[6];

    const int B = in_sizes[0] / (N_ * T_ * FH_);
    const int E = in_sizes[1] / N_;

    static bool attr_done = false;
    const int fused_smem = SMEM_FLOATS * sizeof(float);   // 87,296 B
    if (!attr_done) {
        cudaFuncSetAttribute(fused_kernel, cudaFuncAttributeMaxDynamicSharedMemorySize,
                             fused_smem);
        attr_done = true;
    }

    edge_kernel<<<(E + 127) / 128, 128>>>(rr, rs, E);
    fused_kernel<<<dim3(T_, B), 256, fused_smem>>>(h, Wfc, bfc, aw, abp,
                                                   (float*)d_out, B, E);
}

// round 17
// speedup vs baseline: 1.5891x; 1.5891x over previous
#include <cuda_runtime.h>
#include <math.h>

// Shapes (fixed by setup_inputs): B=4, N=64, T=64, FH=128, FO=64
#define N_  64
#define T_  64
#define FH_ 128
#define FO_ 64

// Scratch (device global; no allocation allowed). Every element [0,E) is
// overwritten by edge_kernel each launch -> no zeroing needed.
__device__ int g_eidx[4096];

// ---------------------------------------------------------------------------
// packed fp32x2 helpers (Blackwell FFMA2 — only reachable via PTX)
// ---------------------------------------------------------------------------
__device__ __forceinline__ unsigned long long fma2(unsigned long long a,
                                                   unsigned long long b,
                                                   unsigned long long c) {
    unsigned long long d;
    asm("fma.rn.f32x2 %0, %1, %2, %3;" : "=l"(d) : "l"(a), "l"(b), "l"(c));
    return d;
}
__device__ __forceinline__ unsigned long long pack2(float x, float y) {
    unsigned long long d;
    asm("mov.b64 %0, {%1, %2};" : "=l"(d)
        : "r"(__float_as_uint(x)), "r"(__float_as_uint(y)));
    return d;
}
__device__ __forceinline__ float lo2(unsigned long long v) {
    return __uint_as_float((unsigned)v);
}
__device__ __forceinline__ float hi2(unsigned long long v) {
    return __uint_as_float((unsigned)(v >> 32));
}

// ---------------------------------------------------------------------------
// Kernel 1: edge indices via argmax. 8 lanes per edge, shuffle reduction.
// rel_rec / rel_send rows are one-hot, so the max (1.0) is strict; first-max
// tie rule still honored (ties only among equal values -> smaller index wins).
// ---------------------------------------------------------------------------
__global__ void edge_kernel(const float* __restrict__ rr,
                            const float* __restrict__ rs, int E)
{
    int g = blockIdx.x * blockDim.x + threadIdx.x;
    int e = g >> 3, sub = g & 7;
    if (e >= E) return;

    const float4* r4 = reinterpret_cast<const float4*>(rr + (size_t)e * N_ + sub * 8);
    const float4* s4 = reinterpret_cast<const float4*>(rs + (size_t)e * N_ + sub * 8);

    float mr = -1e30f, ms = -1e30f;
    int ir = 0, is = 0;
    #pragma unroll
    for (int j = 0; j < 2; j++) {
        float4 v = r4[j];
        int base = sub * 8 + j * 4;
        if (v.x > mr) { mr = v.x; ir = base + 0; }
        if (v.y > mr) { mr = v.y; ir = base + 1; }
        if (v.z > mr) { mr = v.z; ir = base + 2; }
        if (v.w > mr) { mr = v.w; ir = base + 3; }
        float4 w = s4[j];
        if (w.x > ms) { ms = w.x; is = base + 0; }
        if (w.y > ms) { ms = w.y; is = base + 1; }
        if (w.z > ms) { ms = w.z; is = base + 2; }
        if (w.w > ms) { ms = w.w; is = base + 3; }
    }
    // reduce over the 8-lane group (width=8 shuffles)
    #pragma unroll
    for (int off = 4; off >= 1; off >>= 1) {
        float omr = __shfl_down_sync(0xffffffffu, mr, off, 8);
        int   oir = __shfl_down_sync(0xffffffffu, ir, off, 8);
        if (omr > mr || (omr == mr && oir < ir)) { mr = omr; ir = oir; }
        float oms = __shfl_down_sync(0xffffffffu, ms, off, 8);
        int   ois = __shfl_down_sync(0xffffffffu, is, off, 8);
        if (oms > ms || (oms == ms && ois < is)) { ms = oms; is = ois; }
    }
    if (sub == 0) g_eidx[e] = ir * N_ + is;
}

// ---------------------------------------------------------------------------
// Kernel 2: FUSED. One block per (b,t), 256 threads, 3 blocks/SM.
//   P1: stage h[b,:,t,:] -> sh, W^T -> swt, a_w -> saw
//   P2: GEMM1 (4n x 4o, FFMA2) -> regs ; sync ; store swh (OVERLAYS sh) and
//       zero sa (OVERLAYS sh/swt tail)
//   P3: pr/ps = swh · a_r/a_s
//   P4: edge scatter: sa[r][s] += exp(lrelu(pr[r]+ps[s]+ab)) (smem atomics)
//   P5a: row sums -> sinv
//   P5b: ONE pass writes A (raw), A_sym, A_norm (raw*inv); sa stays RAW
//   P6: GEMM2 on raw sa, epilogue scales by sinv[n] then relu
// smem: live = max(GEMM1: sh[8448]+swt[8704], after: swh[4352]+sa[4352])
//       + tail (pr/ps/inv/aw = 320)  -> 17472 floats = 69,888 B
// ---------------------------------------------------------------------------
#define SH_STRIDE  132
#define SWT_STRIDE 68
#define SA_STRIDE  68
#define SWH_STRIDE 68
#define OFF_WT   8448                 // swt after sh
#define OFF_WH   0                    // overlays sh
#define OFF_A    4352                 // overlays sh tail / swt head
#define OFF_PR   17152
#define OFF_PS   (OFF_PR + 64)
#define OFF_INV  (OFF_PS + 64)
#define OFF_AW   (OFF_INV + 64)
#define SMEM_FLOATS (OFF_AW + 128)    // 17472 floats = 69,888 B

__global__ void __launch_bounds__(256, 3)
fused_kernel(const float* __restrict__ h,    // [B][N][T][FH]
             const float* __restrict__ W,    // [FO][FH]
             const float* __restrict__ bfc,  // [FO]
             const float* __restrict__ aw,   // [2*FO]
             const float* __restrict__ ab_ptr,
             float* __restrict__ out, int B, int E)
{
    extern __shared__ float sm[];
    float* sh   = sm;             // [64][132]  (P1-P2 only)
    float* swt  = sm + OFF_WT;    // [128][68]  (P1-P2 only)
    float* swh  = sm + OFF_WH;    // [64][68]   (after GEMM1, overlays sh)
    float* sa   = sm + OFF_A;     // [64][68]   (after GEMM1, overlays sh/swt)
    float* spr  = sm + OFF_PR;
    float* sps  = sm + OFF_PS;
    float* sinv = sm + OFF_INV;
    float* saw  = sm + OFF_AW;    // [128]

    const int t   = blockIdx.x;
    const int b   = blockIdx.y;
    const int tid = threadIdx.x;

    // ---- P1: stage ----
    #pragma unroll
    for (int i = 0; i < 8; i++) {
        int idx = tid + i * 256;          // 0..2047
        int n = idx >> 5, c4 = (idx & 31) * 4;
        float4 v = *reinterpret_cast<const float4*>(
            h + ((size_t)(b * N_ + n) * T_ + t) * FH_ + c4);
        *reinterpret_cast<float4*>(&sh[n * SH_STRIDE + c4]) = v;
    }
    {   // W^T: [k][o]
        int o = tid >> 2, kc = (tid & 3) * 32;
        const float4* wrow = reinterpret_cast<const float4*>(W + o * FH_ + kc);
        #pragma unroll
        for (int j = 0; j < 8; j++) {
            float4 v = wrow[j];
            int k = kc + j * 4;
            swt[(k + 0) * SWT_STRIDE + o] = v.x;
            swt[(k + 1) * SWT_STRIDE + o] = v.y;
            swt[(k + 2) * SWT_STRIDE + o] = v.z;
            swt[(k + 3) * SWT_STRIDE + o] = v.w;
        }
    }
    if (tid < 128) saw[tid] = aw[tid];
    __syncthreads();

    // ---- P2: GEMM1  Wh[n][o] = sum_k h[n][k] * W^T[k][o] + b[o] ----
    const int ni = tid >> 4;     // 0..15 -> rows ni*4 .. ni*4+3
    const int oi = tid & 15;     // 0..15 -> cols oi*4 .. oi*4+3
    const int o0 = oi * 4;
    unsigned long long acc[8];
    {
        unsigned long long bv0 = pack2(bfc[o0 + 0], bfc[o0 + 1]);
        unsigned long long bv1 = pack2(bfc[o0 + 2], bfc[o0 + 3]);
        #pragma unroll
        for (int r = 0; r < 4; r++) { acc[2 * r] = bv0; acc[2 * r + 1] = bv1; }

        const float* hb = sh + (ni * 4) * SH_STRIDE;
        #pragma unroll 4
        for (int k4 = 0; k4 < 32; k4++) {
            float a0[4], a1[4], a2[4], a3[4];
            *reinterpret_cast<float4*>(a0) = *reinterpret_cast<const float4*>(hb + 0 * SH_STRIDE + k4 * 4);
            *reinterpret_cast<float4*>(a1) = *reinterpret_cast<const float4*>(hb + 1 * SH_STRIDE + k4 * 4);
            *reinterpret_cast<float4*>(a2) = *reinterpret_cast<const float4*>(hb + 2 * SH_STRIDE + k4 * 4);
            *reinterpret_cast<float4*>(a3) = *reinterpret_cast<const float4*>(hb + 3 * SH_STRIDE + k4 * 4);
            #pragma unroll
            for (int kk = 0; kk < 4; kk++) {
                ulonglong2 w = *reinterpret_cast<const ulonglong2*>(
                    swt + (k4 * 4 + kk) * SWT_STRIDE + o0);
                unsigned long long h0 = pack2(a0[kk], a0[kk]);
                unsigned long long h1 = pack2(a1[kk], a1[kk]);
                unsigned long long h2 = pack2(a2[kk], a2[kk]);
                unsigned long long h3 = pack2(a3[kk], a3[kk]);
                acc[0] = fma2(h0, w.x, acc[0]); acc[1] = fma2(h0, w.y, acc[1]);
                acc[2] = fma2(h1, w.x, acc[2]); acc[3] = fma2(h1, w.y, acc[3]);
                acc[4] = fma2(h2, w.x, acc[4]); acc[5] = fma2(h2, w.y, acc[5]);
                acc[6] = fma2(h3, w.x, acc[6]); acc[7] = fma2(h3, w.y, acc[7]);
            }
        }
    }
    __syncthreads();   // all reads of sh/swt complete -> safe to overlay

    // store Wh tile into overlay region; zero score tile
    #pragma unroll
    for (int r = 0; r < 4; r++) {
        float4 v = make_float4(lo2(acc[2 * r]), hi2(acc[2 * r]),
                               lo2(acc[2 * r + 1]), hi2(acc[2 * r + 1]));
        *reinterpret_cast<float4*>(swh + (ni * 4 + r) * SWH_STRIDE + o0) = v;
    }
    #pragma unroll
    for (int i = 0; i < 17; i++) sa[tid + i * 256] = 0.f;   // 64*68 = 4352
    __syncthreads();

    // ---- P3: pr/ps from Wh (bias folded in) ----
    if (tid < 128) {
        int n = tid & 63;
        const float* wr = swh + n * SWH_STRIDE;
        const float* av = (tid < 64) ? saw : (saw + 64);
        float a = 0.f;
        #pragma unroll
        for (int j = 0; j < 16; j++) {
            float4 wv  = *reinterpret_cast<const float4*>(wr + j * 4);
            float4 avv = *reinterpret_cast<const float4*>(av + j * 4);
            a = fmaf(wv.x, avv.x, a); a = fmaf(wv.y, avv.y, a);
            a = fmaf(wv.z, avv.z, a); a = fmaf(wv.w, avv.w, a);
        }
        if (tid < 64) spr[n] = a; else sps[n] = a;
    }
    __syncthreads();

    // ---- P4: edge scatter into sa ----
    const float ab = ab_ptr[0];
    for (int e = tid; e < E; e += 256) {
        int idx = g_eidx[e];
        int r = idx >> 6, s = idx & 63;
        float x = spr[r] + sps[s] + ab;
        x = (x > 0.f) ? x : 0.2f * x;
        atomicAdd(&sa[r * SA_STRIDE + s], __expf(x));
    }
    __syncthreads();

    // ---- P5a: row reciprocals ----
    if (tid < 64) {
        const float* row = sa + tid * SA_STRIDE;
        float s0 = 0.f, s1 = 0.f, s2 = 0.f, s3 = 0.f;
        #pragma unroll
        for (int j = 0; j < 16; j++) {
            float4 v = *reinterpret_cast<const float4*>(row + j * 4);
            s0 += v.x; s1 += v.y; s2 += v.z; s3 += v.w;
        }
        sinv[tid] = __fdividef(1.f, (s0 + s1) + (s2 + s3));
    }
    __syncthreads();

    // ---- P5b: ONE pass -> A, A_sym, A_norm (sa stays RAW) ----
    const size_t npp = (size_t)B * T_ * N_ * N_;
    float* A_out     = out + (size_t)B * N_ * T_ * FO_;
    float* Asym_out  = A_out + npp;
    float* Anorm_out = Asym_out + npp;
    const size_t abase = ((size_t)(b * T_ + t)) * (N_ * N_);

    #pragma unroll
    for (int i = 0; i < 16; i++) {
        int idx = tid + i * 256;
        int r = idx >> 6, s = idx & 63;
        float v = sa[r * SA_STRIDE + s];
        A_out[abase + idx]     = v;
        Asym_out[abase + idx]  = 0.5f * (v + sa[s * SA_STRIDE + r]);
        Anorm_out[abase + idx] = v * sinv[r];
    }

    // ---- P6: GEMM2 on raw sa ; epilogue scale by sinv[n], relu ----
    {
        #pragma unroll
        for (int i = 0; i < 8; i++) acc[i] = 0ull;

        const float* arow = sa + (ni * 4) * SA_STRIDE;
        #pragma unroll 4
        for (int m4 = 0; m4 < 16; m4++) {
            float a0[4], a1[4], a2[4], a3[4];
            *reinterpret_cast<float4*>(a0) = *reinterpret_cast<const float4*>(arow + 0 * SA_STRIDE + m4 * 4);
            *reinterpret_cast<float4*>(a1) = *reinterpret_cast<const float4*>(arow + 1 * SA_STRIDE + m4 * 4);
            *reinterpret_cast<float4*>(a2) = *reinterpret_cast<const float4*>(arow + 2 * SA_STRIDE + m4 * 4);
            *reinterpret_cast<float4*>(a3) = *reinterpret_cast<const float4*>(arow + 3 * SA_STRIDE + m4 * 4);
            #pragma unroll
            for (int mm = 0; mm < 4; mm++) {
                ulonglong2 w = *reinterpret_cast<const ulonglong2*>(
                    swh + (m4 * 4 + mm) * SWH_STRIDE + o0);
                unsigned long long h0 = pack2(a0[mm], a0[mm]);
                unsigned long long h1 = pack2(a1[mm], a1[mm]);
                unsigned long long h2 = pack2(a2[mm], a2[mm]);
                unsigned long long h3 = pack2(a3[mm], a3[mm]);
                acc[0] = fma2(h0, w.x, acc[0]); acc[1] = fma2(h0, w.y, acc[1]);
                acc[2] = fma2(h1, w.x, acc[2]); acc[3] = fma2(h1, w.y, acc[3]);
                acc[4] = fma2(h2, w.x, acc[4]); acc[5] = fma2(h2, w.y, acc[5]);
                acc[6] = fma2(h3, w.x, acc[6]); acc[7] = fma2(h3, w.y, acc[7]);
            }
        }
        #pragma unroll
        for (int r = 0; r < 4; r++) {
            int n = ni * 4 + r;
            float inv = sinv[n];
            float4 v = make_float4(fmaxf(lo2(acc[2 * r]) * inv, 0.f),
                                   fmaxf(hi2(acc[2 * r]) * inv, 0.f),
                                   fmaxf(lo2(acc[2 * r + 1]) * inv, 0.f),
                                   fmaxf(hi2(acc[2 * r + 1]) * inv, 0.f));
            *reinterpret_cast<float4*>(out + (size_t)b * (N_ * T_ * FO_)
                                       + (size_t)n * (T_ * FO_)
                                       + (size_t)t * FO_ + o0) = v;
        }
    }
}

// ---------------------------------------------------------------------------
extern "C" void kernel_launch(void* const* d_in, const int* in_sizes, int n_in,
                              void* d_out, int out_size)
{
    const float* h   = (const float*)d_in[0];
    const float* rr  = (const float*)d_in[1];
    const float* rs  = (const float*)d_in[2];
    const float* Wfc = (const float*)d_in[3];
    const float* bfc = (const float*)d_in[4];
    const float* aw  = (const float*)d_in[5];
    const float* abp = (const float*)d_in[6];

    const int B = in_sizes[0] / (N_ * T_ * FH_);
    const int E = in_sizes[1] / N_;

    static bool attr_done = false;
    const int fused_smem = SMEM_FLOATS * sizeof(float);   // 69,888 B
    if (!attr_done) {
        cudaFuncSetAttribute(fused_kernel, cudaFuncAttributeMaxDynamicSharedMemorySize,
                             fused_smem);
        attr_done = true;
    }

    edge_kernel<<<(E * 8 + 255) / 256, 256>>>(rr, rs, E);
    fused_kernel<<<dim3(T_, B), 256, fused_smem>>>(h, Wfc, bfc, aw, abp,
                                                   (float*)d_out, B, E);
}